// round 17
// baseline (speedup 1.0000x reference)
#include <cuda_runtime.h>
#include <cuda_bf16.h>
#include <cstdint>

#define NN 4096
#define DD 256
#define HH 8
#define DHH 32
#define EE 131072
#define BCAP 96

// ---------------- scratch ----------------
__device__ float g_q[HH * NN * DHH];
__device__ float g_v[HH * NN * DHH];
__device__ float g_att[NN * DD];      // unnormalized attn out
__device__ float g_l[HH * NN];        // row sums
__device__ float g_tmp[NN * DD];
// bucketed edge lists keyed by source row
__device__ int g_cnt[NN];
__device__ int g_bkt[NN * BCAP];      // dst | (type<<12)
__device__ int g_ovf[EE];             // (src<<16) | (type<<12) | dst
__device__ int g_ovfn;
// split-bf16 operands
__device__ __nv_bfloat16 g_qs[HH * NN * 64];   // per row: [hi 32][lo 32], q pre-scaled
__device__ __nv_bfloat16 g_ks[HH * NN * 64];   // per row: [hi 32][lo 32 unused]
__device__ __nv_bfloat16 g_vth[HH * 32 * NN];  // V^T hi  [h][d][n]
__device__ __nv_bfloat16 g_vs[HH * NN * 32];   // V hi, row-major [h][n][dh] (for k_corr)

// ---------------- flash3 smem layout (dynamic, double-buffered K-hi/V-hi) ----------------
#define OQ    0
#define OKB   18432                 // K-hi bufs: +bi*10240  (128 x 80B pitch)
#define OVB   38912                 // V-hi bufs: +bi*8704 (32 x 272B)
#define SM3   56320

// ---------------- packed fp32x2 helpers ----------------
#define PACK2(u, lo, hi) asm("mov.b64 %0, {%1,%2};" : "=l"(u) : "f"(lo), "f"(hi))
#define UNPACK2(lo, hi, u) asm("mov.b64 {%0,%1}, %2;" : "=f"(lo), "=f"(hi) : "l"(u))
#define FMA2(d, a, b) asm("fma.rn.f32x2 %0, %1, %2, %0;" : "+l"(d) : "l"(a), "l"(b))

__device__ __forceinline__ uint32_t s2u(const void* p) {
    uint32_t a;
    asm("{ .reg .u64 t; cvta.to.shared.u64 t, %1; cvt.u32.u64 %0, t; }" : "=r"(a) : "l"(p));
    return a;
}

// exp via MUFU pipe (overlaps with FMA + tensor pipes)
__device__ __forceinline__ float mexp(float s) {
    float r;
    asm("ex2.approx.f32 %0, %1;" : "=f"(r) : "f"(s * 1.4426950408889634f));
    return r;
}

#define LDM_X2(r_, a_)                                                         \
    asm volatile("ldmatrix.sync.aligned.m8n8.x2.shared.b16 {%0,%1}, [%2];"     \
                 : "=r"((r_)[0]), "=r"((r_)[1]) : "r"(a_))
#define LDM_X4(r_, a_)                                                         \
    asm volatile("ldmatrix.sync.aligned.m8n8.x4.shared.b16 {%0,%1,%2,%3}, [%4];" \
                 : "=r"((r_)[0]), "=r"((r_)[1]), "=r"((r_)[2]), "=r"((r_)[3]) : "r"(a_))
#define MMA_BF16(c_, a_, b_)                                                   \
    asm volatile("mma.sync.aligned.m16n8k16.row.col.f32.bf16.bf16.f32 "        \
                 "{%0,%1,%2,%3}, {%4,%5,%6,%7}, {%8,%9}, {%0,%1,%2,%3};"       \
                 : "+f"((c_)[0]), "+f"((c_)[1]), "+f"((c_)[2]), "+f"((c_)[3])  \
                 : "r"((a_)[0]), "r"((a_)[1]), "r"((a_)[2]), "r"((a_)[3]),     \
                   "r"((b_)[0]), "r"((b_)[1]))
#define CPA16(dst, src) \
    asm volatile("cp.async.ca.shared.global [%0], [%1], 16;" :: "r"(dst), "l"(src))
#define CPA_COMMIT() asm volatile("cp.async.commit_group;" ::: "memory")
#define CPA_WAIT0() asm volatile("cp.async.wait_group 0;" ::: "memory")
#define CPA_WAIT1() asm volatile("cp.async.wait_group 1;" ::: "memory")

// ---------------- 1. QKV projections (x+pos fused in, split-bf16 fused out) ----------------
__global__ void __launch_bounds__(256) k_qkv(
    const float* __restrict__ x, const float* __restrict__ pos,
    const float* __restrict__ Wq, const float* __restrict__ bq,
    const float* __restrict__ Wk, const float* __restrict__ bk,
    const float* __restrict__ Wv, const float* __restrict__ bv) {
    const int z = blockIdx.z;
    const float* W;
    const float* bias;
    if (z == 0)      { W = Wq; bias = bq; }
    else if (z == 1) { W = Wk; bias = bk; }
    else             { W = Wv; bias = bv; }

    __shared__ __align__(16) float AsT[32][68];   // [k][row]
    __shared__ __align__(16) float Bs2[32][68];   // [k][col]
    const int m0 = blockIdx.y * 64, n0 = blockIdx.x * 64;
    const int tid = threadIdx.x, tx = tid & 15, ty = tid >> 4;

    unsigned long long acc[4][2];
    #pragma unroll
    for (int i = 0; i < 4; i++) { acc[i][0] = 0ull; acc[i][1] = 0ull; }

    for (int kk = 0; kk < DD; kk += 32) {
        #pragma unroll
        for (int i = tid; i < 64 * 32; i += 256) {
            int r = i >> 5, c = i & 31;
            int gi = (m0 + r) * DD + kk + c;
            AsT[c][r] = x[gi] + pos[gi];
        }
        #pragma unroll
        for (int i = tid; i < 32 * 64; i += 256) {
            int r = i >> 6, c = i & 63;
            Bs2[r][c] = W[(kk + r) * DD + n0 + c];
        }
        __syncthreads();
        #pragma unroll 8
        for (int kq = 0; kq < 32; kq++) {
            float4 a = *(const float4*)&AsT[kq][ty * 4];
            ulonglong2 b = *(const ulonglong2*)&Bs2[kq][tx * 4];
            float av[4] = {a.x, a.y, a.z, a.w};
            #pragma unroll
            for (int r = 0; r < 4; r++) {
                unsigned long long ap;
                PACK2(ap, av[r], av[r]);
                FMA2(acc[r][0], ap, b.x);
                FMA2(acc[r][1], ap, b.y);
            }
        }
        __syncthreads();
    }

    const float sc = (z == 0) ? 0.17677669529663687f : 1.0f;
    #pragma unroll
    for (int i = 0; i < 4; i++) {
        int row = m0 + ty * 4 + i;
        float v0, v1, v2, v3;
        UNPACK2(v0, v1, acc[i][0]);
        UNPACK2(v2, v3, acc[i][1]);
        float vv[4] = {v0, v1, v2, v3};
        int col0 = n0 + tx * 4;
        int hh2 = col0 >> 5, dh0 = col0 & 31;
        if (z == 0) {
            // q: fp32 (for k_corr) + scaled hi/lo splits (for flash3)
            #pragma unroll
            for (int j = 0; j < 4; j++) {
                int col = col0 + j;
                float val = vv[j] + bias[col];
                g_q[((size_t)hh2 * NN + row) * DHH + (col & 31)] = val;
                float sv = val * sc;
                __nv_bfloat16 hi = __float2bfloat16(sv);
                size_t base = ((size_t)hh2 * NN + row) * 64 + (col & 31);
                g_qs[base] = hi;
                g_qs[base + 32] = __float2bfloat16(sv - __bfloat162float(hi));
            }
        } else if (z == 1) {
            // k: hi split only (lo never read; fp32 g_k is dead)
            #pragma unroll
            for (int j = 0; j < 4; j++) {
                int col = col0 + j;
                float val = vv[j] + bias[col];
                g_ks[((size_t)hh2 * NN + row) * 64 + (col & 31)] = __float2bfloat16(val);
            }
        } else {
            __nv_bfloat16 hv[4];
            #pragma unroll
            for (int j = 0; j < 4; j++) {
                int col = col0 + j;
                float val = vv[j] + bias[col];
                g_v[((size_t)hh2 * NN + row) * DHH + (col & 31)] = val;
                hv[j] = __float2bfloat16(val);
            }
            *(uint2*)(g_vs + ((size_t)hh2 * NN + row) * 32 + dh0) = *(uint2*)hv;
        }
    }
}

// ---------------- 2. V^T hi split ----------------
__global__ void k_split_vt() {
    int idx = blockIdx.x * 256 + threadIdx.x;     // h*NN+n
    int hh2 = idx >> 12, n = idx & 4095;
    const float* src = g_v + (size_t)idx * 32;
    #pragma unroll
    for (int d = 0; d < 32; d++) {
        g_vth[(size_t)(hh2 * 32 + d) * NN + n] = __float2bfloat16(src[d]);
    }
}

// ---------------- 3. bucketed edge lists ----------------
__global__ void k_zero() {
    int i = blockIdx.x * 256 + threadIdx.x;
    if (i < NN) g_cnt[i] = 0;
    if (i == 0) g_ovfn = 0;
}
__global__ void k_bucket(const int* __restrict__ ei, const int* __restrict__ et) {
    int e = blockIdx.x * 256 + threadIdx.x;
    int src = ei[e];
    int pk = ei[EE + e] | (et[e] << 12);
    int pos = atomicAdd(&g_cnt[src], 1);
    if (pos < BCAP) {
        g_bkt[src * BCAP + pos] = pk;
    } else {
        int op = atomicAdd(&g_ovfn, 1);          // correctness fallback (P ~ 1e-23)
        g_ovf[op] = (src << 16) | pk;
    }
}

// ---------------- 4. dense attention via mma.sync, double-buffered cp.async ----------------
// grid (NN/128, HH), 256 threads (8 warps x 16 rows). O and l written unnormalized.
__global__ void __launch_bounds__(256, 2) k_flash3() {
    extern __shared__ char sm[];
    const uint32_t sb = s2u(sm);
    const int tid = threadIdx.x, w = tid >> 5, lane = tid & 31;
    const int h = blockIdx.y, m0 = blockIdx.x * 128;
    const int g = lane >> 2, c = lane & 3;

    // prologue: Q tile (plain stores) + tile 0 K-hi/V-hi via cp.async group 0
    {
        const uint4* qsrc = ((const uint4*)g_qs) + (size_t)(h * NN + m0) * 8;
        for (int t2 = tid; t2 < 1024; t2 += 256) {
            int r = t2 >> 3, u = t2 & 7;
            *(uint4*)(sm + OQ + r * 144 + u * 16) = qsrc[r * 8 + u];
        }
        const char* ksrc = (const char*)(g_ks + (size_t)(h * NN) * 64);
        for (int t2 = tid; t2 < 512; t2 += 256) {
            int r = t2 >> 2, u = t2 & 3;
            CPA16(sb + OKB + r * 80 + u * 16, ksrc + (size_t)r * 128 + u * 16);
        }
        for (int t2 = tid; t2 < 512; t2 += 256) {
            int d = t2 >> 4, u = t2 & 15;
            size_t go = ((size_t)(h * 32 + d) * NN) * 2 + u * 16;
            CPA16(sb + OVB + d * 272 + u * 16, (const char*)g_vth + go);
        }
        CPA_COMMIT();
        CPA_WAIT0();
    }
    __syncthreads();

    // persistent Q A-fragments: [Qh u0][Qh u1][Ql u0][Ql u1]
    uint32_t qf[4][4];
    {
        int r = (lane & 7) + ((lane >> 3) & 1) * 8;
        uint32_t base = sb + OQ + (w * 16 + r) * 144 + (lane >> 4) * 16;
        #pragma unroll
        for (int s = 0; s < 4; s++) LDM_X4(qf[s], base + s * 32);
    }

    float oacc[4][4];
    #pragma unroll
    for (int d = 0; d < 4; d++)
        #pragma unroll
        for (int i = 0; i < 4; i++) oacc[d][i] = 0.0f;
    float l0 = 0.0f, l1 = 0.0f;

    for (int t = 0; t < 32; t++) {
        __syncthreads();
        if (t + 1 < 32) {
            int jj = (t + 1) * 128, bi = (t + 1) & 1;
            const char* ksrc = (const char*)(g_ks + (size_t)(h * NN + jj) * 64);
            for (int t2 = tid; t2 < 512; t2 += 256) {
                int r = t2 >> 2, u = t2 & 3;
                CPA16(sb + OKB + bi * 10240 + r * 80 + u * 16, ksrc + (size_t)r * 128 + u * 16);
            }
            for (int t2 = tid; t2 < 512; t2 += 256) {
                int d = t2 >> 4, u = t2 & 15;
                size_t go = ((size_t)(h * 32 + d) * NN + jj) * 2 + u * 16;
                CPA16(sb + OVB + bi * 8704 + d * 272 + u * 16, (const char*)g_vth + go);
            }
            CPA_COMMIT();
            CPA_WAIT1();
        } else {
            CPA_WAIT0();
        }
        __syncthreads();

        const int bi = t & 1;
        const uint32_t kbase = sb + OKB + bi * 10240 + (lane & 7) * 80 + ((lane >> 3) & 1) * 16;
        const uint32_t vbh = sb + OVB + bi * 8704 + (lane & 7) * 272 + ((lane >> 3) & 1) * 16;

        #pragma unroll 1
        for (int kg = 0; kg < 8; kg++) {
            // S = (Qh + Ql) * Kh  (K-lo dropped: same rounding class as P-hi)
            float sa[4] = {0.f, 0.f, 0.f, 0.f};
            float sbv[4] = {0.f, 0.f, 0.f, 0.f};
            uint32_t b0[2], b1[2];
            uint32_t ka0 = kbase + (2 * kg) * (8 * 80);
            uint32_t ka1 = kbase + (2 * kg + 1) * (8 * 80);
            LDM_X2(b0, ka0);        LDM_X2(b1, ka0 + 32);
            MMA_BF16(sa, qf[0], b0); MMA_BF16(sa, qf[1], b1);
            MMA_BF16(sa, qf[2], b0); MMA_BF16(sa, qf[3], b1);
            LDM_X2(b0, ka1);        LDM_X2(b1, ka1 + 32);
            MMA_BF16(sbv, qf[0], b0); MMA_BF16(sbv, qf[1], b1);
            MMA_BF16(sbv, qf[2], b0); MMA_BF16(sbv, qf[3], b1);

            // exp on the MUFU pipe (overlaps tensor + FMA work)
            #pragma unroll
            for (int i = 0; i < 4; i++) { sa[i] = mexp(sa[i]); sbv[i] = mexp(sbv[i]); }
            l0 += sa[0] + sa[1] + sbv[0] + sbv[1];
            l1 += sa[2] + sa[3] + sbv[2] + sbv[3];

            // P in bf16 (hi only)
            uint32_t ah[4];
            asm("cvt.rn.bf16x2.f32 %0, %1, %2;" : "=r"(ah[0]) : "f"(sa[1]), "f"(sa[0]));
            asm("cvt.rn.bf16x2.f32 %0, %1, %2;" : "=r"(ah[1]) : "f"(sa[3]), "f"(sa[2]));
            asm("cvt.rn.bf16x2.f32 %0, %1, %2;" : "=r"(ah[2]) : "f"(sbv[1]), "f"(sbv[0]));
            asm("cvt.rn.bf16x2.f32 %0, %1, %2;" : "=r"(ah[3]) : "f"(sbv[3]), "f"(sbv[2]));

            // O += P * V-hi
            #pragma unroll
            for (int d = 0; d < 4; d++) {
                uint32_t vh[2];
                LDM_X2(vh, vbh + d * (8 * 272) + kg * 32);
                MMA_BF16(oacc[d], ah, vh);
            }
        }
    }

    l0 += __shfl_xor_sync(0xffffffffu, l0, 1);
    l0 += __shfl_xor_sync(0xffffffffu, l0, 2);
    l1 += __shfl_xor_sync(0xffffffffu, l1, 1);
    l1 += __shfl_xor_sync(0xffffffffu, l1, 2);
    int row0 = m0 + w * 16 + g;
    if (c == 0) {
        g_l[h * NN + row0] = l0;
        g_l[h * NN + row0 + 8] = l1;
    }
    float* o0 = g_att + (size_t)row0 * DD + h * 32;
    float* o1 = g_att + (size_t)(row0 + 8) * DD + h * 32;
    #pragma unroll
    for (int d = 0; d < 4; d++) {
        *(float2*)(o0 + d * 8 + 2 * c) = make_float2(oacc[d][0], oacc[d][1]);
        *(float2*)(o1 + d * 8 + 2 * c) = make_float2(oacc[d][2], oacc[d][3]);
    }
}

// ---------------- 5. sparse edge-bias correction (per-edge; bf16 K/V) ----------------
__global__ void __launch_bounds__(256) k_corr(const float* __restrict__ emb) {
    int t = blockIdx.x * 256 + threadIdx.x;
    int row = t >> 3, h = t & 7;
    int n = g_cnt[row];
    if (n == 0) return;
    int nb = n < BCAP ? n : BCAP;

    const float* qp = g_q + ((size_t)h * NN + row) * 32;
    float4 qv[8];
    #pragma unroll
    for (int i = 0; i < 8; i++) qv[i] = ((const float4*)qp)[i];
    const __nv_bfloat16* kh_ = g_ks + (size_t)h * NN * 64;   // hi half at row*64
    const __nv_bfloat16* vh_ = g_vs + (size_t)h * NN * 32;

    float4 oa[8];
    #pragma unroll
    for (int i = 0; i < 8; i++) oa[i] = make_float4(0.f, 0.f, 0.f, 0.f);
    float lacc = 0.0f;
    const float scale = 0.17677669529663687f;
    const int* bkt = g_bkt + row * BCAP;

    for (int idx = 0; idx < nb; idx++) {
        int pk = bkt[idx];
        int d = pk & 0xFFF;
        float bs = emb[(pk >> 12) * HH + h];
        const __nv_bfloat162* kp = (const __nv_bfloat162*)(kh_ + (size_t)d * 64);
        float s = 0.0f;
        #pragma unroll
        for (int i = 0; i < 8; i++) {
            float2 a = __bfloat1622float2(kp[2 * i]);
            float2 b = __bfloat1622float2(kp[2 * i + 1]);
            s += qv[i].x * a.x + qv[i].y * a.y + qv[i].z * b.x + qv[i].w * b.y;
        }
        float wgt = __expf(s * scale) * (__expf(bs) - 1.0f);
        lacc += wgt;
        const __nv_bfloat162* vp = (const __nv_bfloat162*)(vh_ + (size_t)d * 32);
        #pragma unroll
        for (int i = 0; i < 8; i++) {
            float2 a = __bfloat1622float2(vp[2 * i]);
            float2 b = __bfloat1622float2(vp[2 * i + 1]);
            oa[i].x += wgt * a.x; oa[i].y += wgt * a.y;
            oa[i].z += wgt * b.x; oa[i].w += wgt * b.y;
        }
    }
    if (n > BCAP) {   // correctness fallback, statistically never taken
        int on = g_ovfn;
        for (int idx = 0; idx < on; idx++) {
            int rec = g_ovf[idx];
            if ((rec >> 16) != row) continue;
            int d = rec & 0xFFF;
            float bs = emb[((rec >> 12) & 0xF) * HH + h];
            const __nv_bfloat162* kp = (const __nv_bfloat162*)(kh_ + (size_t)d * 64);
            float s = 0.0f;
            #pragma unroll
            for (int i = 0; i < 8; i++) {
                float2 a = __bfloat1622float2(kp[2 * i]);
                float2 b = __bfloat1622float2(kp[2 * i + 1]);
                s += qv[i].x * a.x + qv[i].y * a.y + qv[i].z * b.x + qv[i].w * b.y;
            }
            float wgt = __expf(s * scale) * (__expf(bs) - 1.0f);
            lacc += wgt;
            const __nv_bfloat162* vp = (const __nv_bfloat162*)(vh_ + (size_t)d * 32);
            #pragma unroll
            for (int i = 0; i < 8; i++) {
                float2 a = __bfloat1622float2(vp[2 * i]);
                float2 b = __bfloat1622float2(vp[2 * i + 1]);
                oa[i].x += wgt * a.x; oa[i].y += wgt * a.y;
                oa[i].z += wgt * b.x; oa[i].w += wgt * b.y;
            }
        }
    }

    g_l[h * NN + row] += lacc;
    float* dst = g_att + (size_t)row * DD + h * 32;
    #pragma unroll
    for (int i = 0; i < 8; i++) {
        float4 cur = ((float4*)dst)[i];
        ((float4*)dst)[i] = make_float4(cur.x + oa[i].x, cur.y + oa[i].y,
                                        cur.z + oa[i].z, cur.w + oa[i].w);
    }
}

// ---------------- 6. tmp = x + (att/l) @ Wo + bo  (normalization fused) ----------------
__global__ void __launch_bounds__(256) k_oproj(const float* __restrict__ Wo,
                                               const float* __restrict__ bo,
                                               const float* __restrict__ x) {
    __shared__ __align__(16) float AsT[32][68];
    __shared__ __align__(16) float Bs2[32][68];
    __shared__ float invl[64][8];
    const int m0 = blockIdx.y * 64, n0 = blockIdx.x * 64;
    const int tid = threadIdx.x, tx = tid & 15, ty = tid >> 4;

    #pragma unroll
    for (int i = tid; i < 512; i += 256) {
        int r = i >> 3, hh2 = i & 7;
        invl[r][hh2] = 1.0f / g_l[hh2 * NN + m0 + r];
    }
    __syncthreads();

    unsigned long long acc[4][2];
    #pragma unroll
    for (int i = 0; i < 4; i++) { acc[i][0] = 0ull; acc[i][1] = 0ull; }

    for (int kk = 0; kk < DD; kk += 32) {
        #pragma unroll
        for (int i = tid; i < 64 * 32; i += 256) {
            int r = i >> 5, c = i & 31;
            AsT[c][r] = g_att[(m0 + r) * DD + kk + c] * invl[r][(kk + c) >> 5];
        }
        #pragma unroll
        for (int i = tid; i < 32 * 64; i += 256) {
            int r = i >> 6, c = i & 63;
            Bs2[r][c] = Wo[(kk + r) * DD + n0 + c];
        }
        __syncthreads();
        #pragma unroll 8
        for (int kq = 0; kq < 32; kq++) {
            float4 a = *(const float4*)&AsT[kq][ty * 4];
            ulonglong2 b = *(const ulonglong2*)&Bs2[kq][tx * 4];
            float av[4] = {a.x, a.y, a.z, a.w};
            #pragma unroll
            for (int r = 0; r < 4; r++) {
                unsigned long long ap;
                PACK2(ap, av[r], av[r]);
                FMA2(acc[r][0], ap, b.x);
                FMA2(acc[r][1], ap, b.y);
            }
        }
        __syncthreads();
    }
    #pragma unroll
    for (int i = 0; i < 4; i++) {
        int row = m0 + ty * 4 + i;
        float v0, v1, v2, v3;
        UNPACK2(v0, v1, acc[i][0]);
        UNPACK2(v2, v3, acc[i][1]);
        float vv[4] = {v0, v1, v2, v3};
        #pragma unroll
        for (int j = 0; j < 4; j++) {
            int col = n0 + tx * 4 + j;
            g_tmp[(size_t)row * DD + col] = vv[j] + bo[col] + x[(size_t)row * DD + col];
        }
    }
}

// ---------------- 7. LayerNorm ----------------
__global__ void __launch_bounds__(256) k_ln(const float* __restrict__ gamma,
                                            const float* __restrict__ beta,
                                            float* __restrict__ out) {
    const int n = blockIdx.x, tid = threadIdx.x;
    float v = g_tmp[(size_t)n * DD + tid];
    __shared__ float red[8];
    float s = v;
    #pragma unroll
    for (int o = 16; o > 0; o >>= 1) s += __shfl_xor_sync(0xffffffffu, s, o);
    if ((tid & 31) == 0) red[tid >> 5] = s;
    __syncthreads();
    float tot = 0.f;
    #pragma unroll
    for (int i = 0; i < 8; i++) tot += red[i];
    float mu = tot * (1.0f / DD);
    float d = v - mu;
    __syncthreads();
    float sq = d * d;
    #pragma unroll
    for (int o = 16; o > 0; o >>= 1) sq += __shfl_xor_sync(0xffffffffu, sq, o);
    if ((tid & 31) == 0) red[tid >> 5] = sq;
    __syncthreads();
    float tot2 = 0.f;
    #pragma unroll
    for (int i = 0; i < 8; i++) tot2 += red[i];
    float var = tot2 * (1.0f / DD);
    out[(size_t)n * DD + tid] = d * rsqrtf(var + 1e-5f) * gamma[tid] + beta[tid];
}

// ---------------- launch ----------------
extern "C" void kernel_launch(void* const* d_in, const int* in_sizes, int n_in,
                              void* d_out, int out_size) {
    const float* x       = (const float*)d_in[0];
    const float* pos     = (const float*)d_in[1];
    const int* ei        = (const int*)d_in[2];
    const int* et        = (const int*)d_in[3];
    const float* Wq = (const float*)d_in[4];
    const float* bq = (const float*)d_in[5];
    const float* Wk = (const float*)d_in[6];
    const float* bk = (const float*)d_in[7];
    const float* Wv = (const float*)d_in[8];
    const float* bv = (const float*)d_in[9];
    const float* Wo = (const float*)d_in[10];
    const float* bo = (const float*)d_in[11];
    const float* emb   = (const float*)d_in[12];
    const float* gamma = (const float*)d_in[13];
    const float* beta  = (const float*)d_in[14];
    float* out = (float*)d_out;

    cudaFuncSetAttribute(k_flash3, cudaFuncAttributeMaxDynamicSharedMemorySize, SM3);

    k_qkv<<<dim3(DD / 64, NN / 64, 3), 256>>>(x, pos, Wq, bq, Wk, bk, Wv, bv);
    k_split_vt<<<HH * NN / 256, 256>>>();
    k_zero<<<(NN + 255) / 256, 256>>>();
    k_bucket<<<EE / 256, 256>>>(ei, et);
    k_flash3<<<dim3(NN / 128, HH), 256, SM3>>>();
    k_corr<<<(NN * HH) / 256, 256>>>(emb);
    k_oproj<<<dim3(DD / 64, NN / 64), 256>>>(Wo, bo, x);
    k_ln<<<NN, 256>>>(gamma, beta, out);
}